// round 1
// baseline (speedup 1.0000x reference)
#include <cuda_runtime.h>
#include <math.h>

#define Nn 64
#define Cc 256
#define Tt 64
#define Vv 25
#define HID 16
#define NG 5
#define TV (Tt*Vv)   // 1600

// Scratch (allowed: __device__ globals, no allocation)
__device__ float g_avg[Nn*Cc];
__device__ float g_max[Nn*Cc];
__device__ float g_gates[Nn*NG*Cc];

// Output joint permutation (concat order) and group id per output position
__constant__ int c_perm[Vv] = {0,1,2,3,20, 8,9,10,11,23,24, 16,17,18,19, 4,5,6,7,21,22, 12,13,14,15};
__constant__ int c_grp [Vv] = {0,0,0,0,0,  1,1,1,1,1,1,     2,2,2,2,     3,3,3,3,3,3,   4,4,4,4};

// ---------------------------------------------------------------------------
// K1: per-(n,c) mean + max over torso joints {0,1,2,3,20} across T.
// One thread per (n,c,t): 5 scalar loads; warp+shared reduce over t.
// block = (64 t-lanes, 4 nc), grid = N*C/4.
// ---------------------------------------------------------------------------
__global__ void k_reduce(const float* __restrict__ x) {
    int nc = blockIdx.x * 4 + threadIdx.y;
    int t  = threadIdx.x;   // 0..63
    const float* p = x + (size_t)nc * TV + t * Vv;
    float v0 = p[0], v1 = p[1], v2 = p[2], v3 = p[3], v4 = p[20];
    float s = ((v0 + v1) + (v2 + v3)) + v4;
    float m = fmaxf(fmaxf(fmaxf(v0, v1), fmaxf(v2, v3)), v4);
    #pragma unroll
    for (int o = 16; o > 0; o >>= 1) {
        s += __shfl_xor_sync(0xFFFFFFFFu, s, o);
        m  = fmaxf(m, __shfl_xor_sync(0xFFFFFFFFu, m, o));
    }
    __shared__ float sh_s[8], sh_m[8];
    int lin = threadIdx.y * 64 + threadIdx.x;
    int wid = lin >> 5;
    if ((threadIdx.x & 31) == 0) { sh_s[wid] = s; sh_m[wid] = m; }
    __syncthreads();
    if (threadIdx.x == 0) {
        float S = sh_s[2*threadIdx.y] + sh_s[2*threadIdx.y + 1];
        float M = fmaxf(sh_m[2*threadIdx.y], sh_m[2*threadIdx.y + 1]);
        g_avg[nc] = S * (1.0f / 320.0f);   // mean over T*5 = 320
        g_max[nc] = M;
    }
}

// ---------------------------------------------------------------------------
// K2: gates[n,f,c] = sigmoid( mlp_f(avg[n,:]) + mlp_f(max[n,:]) )
//   h = relu(in @ W1[f]^T + b1[f])  (HID=16);  out = h @ W2[f]^T + b2[f]
//   => gate = sigmoid( sum_j (hA[f,j]+hM[f,j]) * W2[f,c,j] + 2*b2[f,c] )
// One block per n, 256 threads (8 warps).
// ---------------------------------------------------------------------------
__global__ void k_mlp(const float* __restrict__ W1s, const float* __restrict__ b1s,
                      const float* __restrict__ W2s, const float* __restrict__ b2s) {
    int n   = blockIdx.x;
    int tid = threadIdx.x;
    __shared__ float sA[Cc], sM[Cc], hs[NG*HID];

    sA[tid] = g_avg[n*Cc + tid];
    sM[tid] = g_max[n*Cc + tid];
    __syncthreads();

    int warp = tid >> 5, lane = tid & 31;
    // 80 (f,j) tasks, 10 per warp; each task: two 256-length dots via warp reduce
    for (int task = warp; task < NG*HID; task += 8) {
        const float* w1 = W1s + task * Cc;  // task = f*HID + j, row contiguous over c
        float a = 0.f, m = 0.f;
        #pragma unroll
        for (int k = 0; k < 8; k++) {
            float w = w1[lane + 32*k];
            a += sA[lane + 32*k] * w;
            m += sM[lane + 32*k] * w;
        }
        #pragma unroll
        for (int o = 16; o > 0; o >>= 1) {
            a += __shfl_xor_sync(0xFFFFFFFFu, a, o);
            m += __shfl_xor_sync(0xFFFFFFFFu, m, o);
        }
        if (lane == 0) {
            float b = b1s[task];
            hs[task] = fmaxf(a + b, 0.f) + fmaxf(m + b, 0.f);
        }
    }
    __syncthreads();

    int c = tid;
    #pragma unroll
    for (int f = 0; f < NG; f++) {
        const float4* w2 = reinterpret_cast<const float4*>(W2s + ((size_t)(f*Cc + c)) * HID);
        float acc = 2.0f * b2s[f*Cc + c];
        #pragma unroll
        for (int q = 0; q < 4; q++) {
            float4 w = w2[q];
            acc += hs[f*HID + 4*q + 0] * w.x;
            acc += hs[f*HID + 4*q + 1] * w.y;
            acc += hs[f*HID + 4*q + 2] * w.z;
            acc += hs[f*HID + 4*q + 3] * w.w;
        }
        g_gates[(n*NG + f)*Cc + c] = 1.0f / (1.0f + expf(-acc));
    }
}

// ---------------------------------------------------------------------------
// K3: out[n,c,t,vo] = x[n,c,t,perm[vo]] * gate[n, grp[vo], c]
// One block per (n,c): slice of 1600 floats in/out, gates broadcast via shared.
// ---------------------------------------------------------------------------
__global__ void k_apply(const float* __restrict__ x, float* __restrict__ out) {
    int nc = blockIdx.x;
    int n = nc >> 8, c = nc & 255;
    __shared__ float sg[NG];
    __shared__ int sp[Vv], sgr[Vv];
    if (threadIdx.x < NG)  sg[threadIdx.x]  = g_gates[(n*NG + threadIdx.x)*Cc + c];
    if (threadIdx.x < Vv) { sp[threadIdx.x] = c_perm[threadIdx.x];
                            sgr[threadIdx.x] = c_grp[threadIdx.x]; }
    __syncthreads();
    const float* px = x   + (size_t)nc * TV;
    float*       po = out + (size_t)nc * TV;
    #pragma unroll
    for (int r = 0; r < 7; r++) {
        int i = threadIdx.x + r * 256;
        if (i < TV) {
            int t  = i / 25;
            int vo = i - t * 25;
            po[i] = px[t * 25 + sp[vo]] * sg[sgr[vo]];
        }
    }
}

extern "C" void kernel_launch(void* const* d_in, const int* in_sizes, int n_in,
                              void* d_out, int out_size) {
    const float* x   = (const float*)d_in[0];
    const float* W1s = (const float*)d_in[1];
    const float* b1s = (const float*)d_in[2];
    const float* W2s = (const float*)d_in[3];
    const float* b2s = (const float*)d_in[4];
    float* out = (float*)d_out;

    k_reduce<<<(Nn*Cc)/4, dim3(64, 4)>>>(x);
    k_mlp<<<Nn, 256>>>(W1s, b1s, W2s, b2s);
    k_apply<<<Nn*Cc, 256>>>(x, out);
}